// round 16
// baseline (speedup 1.0000x reference)
#include <cuda_runtime.h>

// Problem constants
#define TT 1024   // T: tickers / states
#define MM 8      // M: mesa rank
#define NN 32768  // N: samples
#define DD 32     // D: input dim
#define HH 64     // H: hidden dim
#define SS 2177   // S = H*D + H + O*H + O
#define SP 2192   // padded state row stride (float4-aligned)
#define CAP 128   // bucket capacity per ticker

#define STATE_BLOCKS 288   // 32-ticker tiles x 9 dst-tiles (best measured)
#define SCAT_BLOCKS  32    // 32768 / (4 * 256)

// Scratch (__device__ globals; d_count zero-init at load, reset by k_compute)
__device__ int   d_count[TT];
__device__ int   d_bucket[TT * CAP];
__device__ float d_states[TT * SP];   // rows stored in PERMUTED (j*64+h) order

__device__ __forceinline__ unsigned long long fma2(
    unsigned long long a, unsigned long long b, unsigned long long c) {
    unsigned long long d;
    asm("fma.rn.f32x2 %0, %1, %2, %3;" : "=l"(d) : "l"(a), "l"(b), "l"(c));
    return d;
}
__device__ __forceinline__ unsigned long long dup2(float v) {
    unsigned long long d;
    asm("mov.b64 %0, {%1, %1};" : "=l"(d) : "f"(v));
    return d;
}

// ---------------------------------------------------------------------------
// k_prep (best-measured config, unchanged): blocks [0,288) build effective
// states in PERMUTED layout: row[d], d = j*64 + h holds w1_eff[h][j]
// (d < 2048); row[d] = state[d] for d in [2048,2177) (b1 | w2 | b2).
// blocks [288,320): bucket-scatter samples by ticker.
// ---------------------------------------------------------------------------
__global__ __launch_bounds__(256) void k_prep(
    const int*   __restrict__ ticker,
    const float* __restrict__ mesa,   // (M, T)
    const float* __restrict__ meta,   // (S, M)
    const float* __restrict__ bias,   // (S,)
    const float* __restrict__ base)   // (S,)
{
    int b   = blockIdx.x;
    int tid = threadIdx.x;

    if (b < STATE_BLOCKS) {
        __shared__ float4 sc4[32][2];     // mesa coeffs for 32 tickers
        int tt = b / 9, st = b % 9;
        int t0 = tt * 32;
        {
            int m = tid >> 5, i = tid & 31;
            ((float*)sc4)[i * 8 + m] = mesa[m * TT + t0 + i];
        }
        __syncthreads();

        int d = st * 256 + tid;           // destination index in permuted row
        int s;
        bool ok = true;
        if (d < 2048) {                   // w1: d = j*64 + h  <->  s = h*32 + j
            int h = d & 63, j = d >> 6;
            s = h * 32 + j;
        } else {
            s = d;
            ok = (d < SS);
        }
        if (ok) {
            const float4* m4 = (const float4*)(meta + s * MM);
            float4 a = m4[0], bq = m4[1];
            float bb = base[s] + bias[s];
#pragma unroll
            for (int i = 0; i < 32; i++) {
                float4 c0 = sc4[i][0];    // broadcast LDS.128
                float4 c1 = sc4[i][1];
                float v = bb
                    + c0.x * a.x + c0.y * a.y + c0.z * a.z + c0.w * a.w
                    + c1.x * bq.x + c1.y * bq.y + c1.z * bq.z + c1.w * bq.w;
                d_states[(t0 + i) * SP + d] = v;   // coalesced over d
            }
        }
    } else {
        int idx = (b - STATE_BLOCKS) * 256 + tid;
        int4 v = ((const int4*)ticker)[idx];
        int n0 = idx * 4;
        int p;
        p = atomicAdd(&d_count[v.x], 1); if (p < CAP) d_bucket[v.x * CAP + p] = n0;
        p = atomicAdd(&d_count[v.y], 1); if (p < CAP) d_bucket[v.y * CAP + p] = n0 + 1;
        p = atomicAdd(&d_count[v.z], 1); if (p < CAP) d_bucket[v.z * CAP + p] = n0 + 2;
        p = atomicAdd(&d_count[v.w], 1); if (p < CAP) d_bucket[v.w * CAP + p] = n0 + 3;
    }
}

// ---------------------------------------------------------------------------
// k_compute: one warp per ticker, DUAL-PATH group sizing.
//   cnt <= 32 : Path A -- exact R5 single 32-sample group (common case, 53%).
//   cnt >  32 : Path B -- 64-sample groups, TWO samples per lane, 64 f32x2
//               accumulators. Each weight LDS.128 feeds 4 FFMA2 (vs 2), so
//               the warps that set the kernel's critical path (they used to
//               run 2 full groups) now run ~1.5 group-equivalents.
// smem floats: s_w [0,2048) wint (j*64+h), [2048,2112) b1, [2112,2176) w2,
// 2176 b2. s_x: 64 rows x stride 33 (each scalar LDS is conflict-free).
// ---------------------------------------------------------------------------
__global__ __launch_bounds__(32) void k_compute(
    const float* __restrict__ x,
    float* __restrict__ out)
{
    __shared__ __align__(16) float s_w[2180];
    __shared__ float s_x[64 * 33];
    __shared__ int   s_n[64];

    int t    = blockIdx.x;
    int lane = threadIdx.x;

    // Coalesced copy of the permuted state row (545 float4 -> 18 iterations).
    const float4* row4 = (const float4*)(d_states + (size_t)t * SP);
    float4* s_w4 = (float4*)s_w;
#pragma unroll
    for (int i = 0; i < 18; i++) {
        int idx = lane + i * 32;
        if (idx < 545) s_w4[idx] = row4[idx];
    }

    int cnt = 0;
    if (lane == 0) { cnt = d_count[t]; d_count[t] = 0; }
    cnt = __shfl_sync(0xffffffffu, cnt, 0);
    if (cnt > CAP) cnt = CAP;
    __syncwarp();
    if (cnt == 0) return;

    const unsigned long long* b1p =
        (const unsigned long long*)(s_w + 2048);     // b1 as f32x2 pairs
    float b2 = s_w[2176];
    const int* bucket = d_bucket + t * CAP;

    if (cnt <= 32) {
        // ---------------- Path A: exact R5 single group ----------------
        bool valid = lane < cnt;
        int n = bucket[valid ? lane : cnt - 1];
        s_n[lane] = n;
        __syncwarp();
#pragma unroll
        for (int k = 0; k < 32; k++) {
            int nk = s_n[k];                          // broadcast LDS
            s_x[k * 33 + lane] = x[nk * DD + lane];   // coalesced 128B rows
        }
        __syncwarp();

        unsigned long long acc[32];
#pragma unroll
        for (int hp = 0; hp < 32; hp++) acc[hp] = b1p[hp];

#pragma unroll 8
        for (int j = 0; j < 32; j++) {
            float xj = s_x[lane * 33 + j];            // conflict-free scalar LDS
            unsigned long long xd = dup2(xj);
            const ulonglong2* wr = (const ulonglong2*)(s_w + j * 64);
#pragma unroll
            for (int hq = 0; hq < 16; hq++) {
                ulonglong2 w = wr[hq];                // broadcast LDS.128
                acc[2 * hq]     = fma2(w.x, xd, acc[2 * hq]);
                acc[2 * hq + 1] = fma2(w.y, xd, acc[2 * hq + 1]);
            }
        }

        float o = b2;
#pragma unroll
        for (int hp = 0; hp < 32; hp++) {
            float lo = __uint_as_float((unsigned)(acc[hp] & 0xffffffffu));
            float hi = __uint_as_float((unsigned)(acc[hp] >> 32));
            o += fmaxf(lo, 0.f) * s_w[2112 + 2 * hp]
               + fmaxf(hi, 0.f) * s_w[2112 + 2 * hp + 1];
        }
        if (valid) out[n] = o;
    } else {
        // ------------- Path B: 64-sample groups, 2 samples/lane -------------
        for (int base = 0; base < cnt; base += 64) {
            int idx0 = base + lane;
            int idx1 = base + 32 + lane;
            bool v0 = idx0 < cnt, v1 = idx1 < cnt;
            int n0 = bucket[v0 ? idx0 : cnt - 1];
            int n1 = bucket[v1 ? idx1 : cnt - 1];

            __syncwarp();                  // prior group done with s_n/s_x
            s_n[lane] = n0;
            s_n[32 + lane] = n1;
            __syncwarp();
#pragma unroll
            for (int k = 0; k < 64; k++) {
                int nk = s_n[k];                          // broadcast LDS
                s_x[k * 33 + lane] = x[nk * DD + lane];   // coalesced rows
            }
            __syncwarp();

            unsigned long long acc[64];                   // 128 regs
#pragma unroll
            for (int hp = 0; hp < 32; hp++) {
                unsigned long long b = b1p[hp];
                acc[hp] = b;
                acc[32 + hp] = b;
            }

#pragma unroll 4
            for (int j = 0; j < 32; j++) {
                unsigned long long xd0 = dup2(s_x[lane * 33 + j]);
                unsigned long long xd1 = dup2(s_x[(32 + lane) * 33 + j]);
                const ulonglong2* wr = (const ulonglong2*)(s_w + j * 64);
#pragma unroll
                for (int hq = 0; hq < 16; hq++) {
                    ulonglong2 w = wr[hq];                // one load, 4 FFMA2
                    acc[2 * hq]          = fma2(w.x, xd0, acc[2 * hq]);
                    acc[2 * hq + 1]      = fma2(w.y, xd0, acc[2 * hq + 1]);
                    acc[32 + 2 * hq]     = fma2(w.x, xd1, acc[32 + 2 * hq]);
                    acc[32 + 2 * hq + 1] = fma2(w.y, xd1, acc[32 + 2 * hq + 1]);
                }
            }

            float o0 = b2, o1 = b2;
#pragma unroll
            for (int hp = 0; hp < 32; hp++) {
                float w2a = s_w[2112 + 2 * hp];
                float w2b = s_w[2112 + 2 * hp + 1];
                unsigned long long a0 = acc[hp], a1 = acc[32 + hp];
                o0 += fmaxf(__uint_as_float((unsigned)(a0 & 0xffffffffu)), 0.f) * w2a
                    + fmaxf(__uint_as_float((unsigned)(a0 >> 32)), 0.f) * w2b;
                o1 += fmaxf(__uint_as_float((unsigned)(a1 & 0xffffffffu)), 0.f) * w2a
                    + fmaxf(__uint_as_float((unsigned)(a1 >> 32)), 0.f) * w2b;
            }
            if (v0) out[n0] = o0;
            if (v1) out[n1] = o1;
        }
    }
}

extern "C" void kernel_launch(void* const* d_in, const int* in_sizes, int n_in,
                              void* d_out, int out_size) {
    const float* x    = (const float*)d_in[0];
    const int*   tick = (const int*)d_in[1];
    const float* mesa = (const float*)d_in[2];   // (M, T)
    const float* meta = (const float*)d_in[3];   // (S, M)
    const float* bias = (const float*)d_in[4];   // (S,)
    const float* base = (const float*)d_in[5];   // (S,)
    float* out = (float*)d_out;                  // (N, 1) float32

    k_prep<<<STATE_BLOCKS + SCAT_BLOCKS, 256>>>(tick, mesa, meta, bias, base);
    k_compute<<<TT, 32>>>(x, out);
}